// round 9
// baseline (speedup 1.0000x reference)
#include <cuda_runtime.h>
#include <cuda_bf16.h>

// Problem constants (fixed by setup_inputs)
#define BB 8
#define T1 256
#define T2 1024
#define CC 128
#define NDIAG (T1 + T2 - 1)   // 1279

#define BIGF 10000000.0f
#define WPF  1.0f

// Phase-1 tiling
#define TJ 64
#define TI 128
#define KC 16

// Scratch (allocation-free rule: __device__ globals)
__device__ float g_cost[BB * T1 * T2];   // [b][j][i]  (T1-major => each DTW thread reads its own contiguous row)
__device__ float g_loss[BB];

// ---------------------------------------------------------------------------
// Phase 1: cost[b][j][i] = mean_c |A[b][j][c] - B[b][i][c]|
// GEMM-style smem tiling, 4x8 register blocking per thread, fp32 fma-pipe bound.
// ---------------------------------------------------------------------------
__global__ __launch_bounds__(256) void cost_kernel(const float* __restrict__ A,
                                                   const float* __restrict__ Bf) {
    __shared__ float As[KC][TJ + 4];   // [k][j], pad keeps 16B align, 2-way STS conflict max
    __shared__ float Bs[KC][TI + 4];   // [k][i]

    const int b  = blockIdx.z;
    const int jb = blockIdx.y * TJ;
    const int ib = blockIdx.x * TI;
    const int tid = threadIdx.x;

    const int kl = tid & 15;     // k lane for loads
    const int rl = tid >> 4;     // row lane for loads (0..15)

    const int tx = tid & 15;     // i-group
    const int ty = tid >> 4;     // j-group
    const int j0 = ty * 4;
    const int i0 = tx * 8;

    const float* Ag = A + (size_t)(b * T1 + jb) * CC;
    const float* Bg = Bf + (size_t)(b * T2 + ib) * CC;

    float acc[4][8];
#pragma unroll
    for (int u = 0; u < 4; u++)
#pragma unroll
        for (int v = 0; v < 8; v++) acc[u][v] = 0.0f;

    for (int c0 = 0; c0 < CC; c0 += KC) {
        // Load A tile: 64 rows x 16 k (4 elems/thread), coalesced 64B per row-chunk
#pragma unroll
        for (int p = 0; p < 4; p++) {
            int jj = rl + p * 16;
            As[kl][jj] = Ag[jj * CC + c0 + kl];
        }
        // Load B tile: 128 rows x 16 k (8 elems/thread)
#pragma unroll
        for (int p = 0; p < 8; p++) {
            int ii = rl + p * 16;
            Bs[kl][ii] = Bg[ii * CC + c0 + kl];
        }
        __syncthreads();

#pragma unroll
        for (int kk = 0; kk < KC; kk++) {
            float4 a4 = *(const float4*)&As[kk][j0];
            float4 b0 = *(const float4*)&Bs[kk][i0];
            float4 b1 = *(const float4*)&Bs[kk][i0 + 4];
            float av[4] = {a4.x, a4.y, a4.z, a4.w};
            float bv[8] = {b0.x, b0.y, b0.z, b0.w, b1.x, b1.y, b1.z, b1.w};
#pragma unroll
            for (int u = 0; u < 4; u++)
#pragma unroll
                for (int v = 0; v < 8; v++)
                    acc[u][v] += fabsf(av[u] - bv[v]);
        }
        __syncthreads();
    }

    const float sc = 1.0f / (float)CC;
#pragma unroll
    for (int u = 0; u < 4; u++) {
        float* dst = g_cost + (size_t)((b * T1 + jb + j0 + u) * T2) + ib + i0;
        float4 o0 = make_float4(acc[u][0] * sc, acc[u][1] * sc, acc[u][2] * sc, acc[u][3] * sc);
        float4 o1 = make_float4(acc[u][4] * sc, acc[u][5] * sc, acc[u][6] * sc, acc[u][7] * sc);
        *(float4*)dst = o0;
        *(float4*)(dst + 4) = o1;
    }
}

// ---------------------------------------------------------------------------
// Phase 2: anti-diagonal soft-DTW wavefront. One block per batch, one thread
// per j-column. 3 rotating smem diag buffers => 1 barrier/diag. 4-deep register
// prefetch of the per-thread cost row hides L2 latency.
// ---------------------------------------------------------------------------
__device__ __forceinline__ float ldc_clamped(const float* __restrict__ row, int i) {
    i = min(max(i, 0), T2 - 1);
    return __ldg(row + i);
}

__global__ __launch_bounds__(T1) void dtw_kernel(const int* __restrict__ len_a,
                                                 const int* __restrict__ len_b) {
    const int b = blockIdx.x;
    const int j = threadIdx.x;                 // 0..255

    __shared__ float sbuf[3 * (T1 + 1)];       // three diag buffers of 257

    const float* __restrict__ crow = g_cost + (size_t)(b * T1 + j) * T2;

    // Init: diag(-1) = pc0 (all BIG); diag(-2) = pcp0 (BIG except [0]=0)
    sbuf[2 * (T1 + 1) + j] = BIGF;
    sbuf[1 * (T1 + 1) + j] = (j == 0) ? 0.0f : BIGF;
    if (j == 0) {
        sbuf[2 * (T1 + 1) + T1] = BIGF;
        sbuf[1 * (T1 + 1) + T1] = BIGF;
    }

    const int la = len_a[b];
    const int lb = len_b[b];
    const int dtarget = la + lb - 2;
    const bool wr = (j == la - 1);

    int pwo = 2 * (T1 + 1);   // diag d-1 ("pc")
    int p1o = 1 * (T1 + 1);   // diag d-2 ("pcp")
    int p2o = 0;              // write target (diag d)
    int dcur = 0;

    __syncthreads();

    // softmin over exactly the reference's 3-value multiset:
    // {v0,v1,v2} == {max(v0,v1), min(min(v0,v1),v2), max(min(v0,v1),v2)}  (exact)
#define STEP(CD) do {                                                        \
        float v0 = sbuf[p1o + j];                                            \
        float v1 = sbuf[pwo + j + 1] + WPF;                                  \
        float v2 = sbuf[pwo + j] + WPF;                                      \
        float mn01 = fminf(v0, v1);                                          \
        float mx01 = fmaxf(v0, v1);                                          \
        float m    = fminf(mn01, v2);                                        \
        float oth  = fmaxf(mn01, v2);                                        \
        float s = 1.0f + __expf((m - mx01) * 100.0f)                         \
                       + __expf((m - oth)  * 100.0f);                        \
        float nv = (CD) + (m - 0.01f * __logf(s));                           \
        sbuf[p2o + j + 1] = nv;                                              \
        if (j == 0) sbuf[p2o] = BIGF;                                        \
        if (wr && dcur == dtarget) g_loss[b] = nv;                           \
        __syncthreads();                                                     \
        int _t = p2o; p2o = p1o; p1o = pwo; pwo = _t;                        \
        dcur++;                                                              \
    } while (0)

    // Prime the 4-deep cost pipeline (i = d - j, clamped exactly like reference)
    float c0 = ldc_clamped(crow, 0 - j);
    float c1 = ldc_clamped(crow, 1 - j);
    float c2 = ldc_clamped(crow, 2 - j);
    float c3 = ldc_clamped(crow, 3 - j);

    const int NGRP = NDIAG / 4;   // 319 full groups => d = 0..1275
    for (int g = 0; g < NGRP; g++) {
        int ip = dcur + 4 - j;
        float n0 = ldc_clamped(crow, ip);
        float n1 = ldc_clamped(crow, ip + 1);
        float n2 = ldc_clamped(crow, ip + 2);
        float n3 = ldc_clamped(crow, ip + 3);
        STEP(c0); STEP(c1); STEP(c2); STEP(c3);
        c0 = n0; c1 = n1; c2 = n2; c3 = n3;
    }
    // Remainder: d = 1276, 1277, 1278
    STEP(c0); STEP(c1); STEP(c2);
#undef STEP
}

// ---------------------------------------------------------------------------
// Phase 3: deterministic fixed-order reduction of the 8 per-batch losses.
// ---------------------------------------------------------------------------
__global__ void reduce_kernel(float* __restrict__ out) {
    float s = 0.0f;
#pragma unroll
    for (int i = 0; i < BB; i++) s += g_loss[i];
    out[0] = s;
}

// ---------------------------------------------------------------------------
extern "C" void kernel_launch(void* const* d_in, const int* in_sizes, int n_in,
                              void* d_out, int out_size) {
    (void)in_sizes; (void)n_in; (void)out_size;
    const float* fa = (const float*)d_in[0];   // fea_a  [8,256,128] f32
    const int*   la = (const int*)  d_in[1];   // len_a  [8] i32
    const float* fb = (const float*)d_in[2];   // fea_b  [8,1024,128] f32
    const int*   lb = (const int*)  d_in[3];   // len_b  [8] i32

    dim3 g1(T2 / TI, T1 / TJ, BB);             // (8,4,8) = 256 blocks
    cost_kernel<<<g1, 256>>>(fa, fb);
    dtw_kernel<<<BB, T1>>>(la, lb);
    reduce_kernel<<<1, 1>>>((float*)d_out);
}

// round 10
// speedup vs baseline: 1.0028x; 1.0028x over previous
#include <cuda_runtime.h>
#include <cuda_bf16.h>

// Problem constants (fixed by setup_inputs)
#define BB 8
#define T1 256
#define T2 1024
#define CC 128
#define NDIAG (T1 + T2 - 1)   // 1279

#define BIGF 10000000.0f
#define WPF  1.0f

// Phase-1 tiling
#define TJ 64
#define TI 128
#define KC 16

// Scratch (allocation-free rule: __device__ globals)
__device__ float g_cost[BB * T1 * T2];   // [b][j][i]  (T1-major => each DTW thread reads its own contiguous row)
__device__ float g_loss[BB];

// ---------------------------------------------------------------------------
// Phase 1: cost[b][j][i] = mean_c |A[b][j][c] - B[b][i][c]|
// GEMM-style smem tiling, 4x8 register blocking per thread, fp32 fma-pipe bound.
// ---------------------------------------------------------------------------
__global__ __launch_bounds__(256) void cost_kernel(const float* __restrict__ A,
                                                   const float* __restrict__ Bf) {
    __shared__ float As[KC][TJ + 4];   // [k][j], pad keeps 16B align, 2-way STS conflict max
    __shared__ float Bs[KC][TI + 4];   // [k][i]

    const int b  = blockIdx.z;
    const int jb = blockIdx.y * TJ;
    const int ib = blockIdx.x * TI;
    const int tid = threadIdx.x;

    const int kl = tid & 15;     // k lane for loads
    const int rl = tid >> 4;     // row lane for loads (0..15)

    const int tx = tid & 15;     // i-group
    const int ty = tid >> 4;     // j-group
    const int j0 = ty * 4;
    const int i0 = tx * 8;

    const float* Ag = A + (size_t)(b * T1 + jb) * CC;
    const float* Bg = Bf + (size_t)(b * T2 + ib) * CC;

    float acc[4][8];
#pragma unroll
    for (int u = 0; u < 4; u++)
#pragma unroll
        for (int v = 0; v < 8; v++) acc[u][v] = 0.0f;

    for (int c0 = 0; c0 < CC; c0 += KC) {
        // Load A tile: 64 rows x 16 k (4 elems/thread), coalesced 64B per row-chunk
#pragma unroll
        for (int p = 0; p < 4; p++) {
            int jj = rl + p * 16;
            As[kl][jj] = Ag[jj * CC + c0 + kl];
        }
        // Load B tile: 128 rows x 16 k (8 elems/thread)
#pragma unroll
        for (int p = 0; p < 8; p++) {
            int ii = rl + p * 16;
            Bs[kl][ii] = Bg[ii * CC + c0 + kl];
        }
        __syncthreads();

#pragma unroll
        for (int kk = 0; kk < KC; kk++) {
            float4 a4 = *(const float4*)&As[kk][j0];
            float4 b0 = *(const float4*)&Bs[kk][i0];
            float4 b1 = *(const float4*)&Bs[kk][i0 + 4];
            float av[4] = {a4.x, a4.y, a4.z, a4.w};
            float bv[8] = {b0.x, b0.y, b0.z, b0.w, b1.x, b1.y, b1.z, b1.w};
#pragma unroll
            for (int u = 0; u < 4; u++)
#pragma unroll
                for (int v = 0; v < 8; v++)
                    acc[u][v] += fabsf(av[u] - bv[v]);
        }
        __syncthreads();
    }

    const float sc = 1.0f / (float)CC;
#pragma unroll
    for (int u = 0; u < 4; u++) {
        float* dst = g_cost + (size_t)((b * T1 + jb + j0 + u) * T2) + ib + i0;
        float4 o0 = make_float4(acc[u][0] * sc, acc[u][1] * sc, acc[u][2] * sc, acc[u][3] * sc);
        float4 o1 = make_float4(acc[u][4] * sc, acc[u][5] * sc, acc[u][6] * sc, acc[u][7] * sc);
        *(float4*)dst = o0;
        *(float4*)(dst + 4) = o1;
    }
}

// ---------------------------------------------------------------------------
// Phase 2: anti-diagonal soft-DTW wavefront. One block per batch, one thread
// per j-column. 3 rotating smem diag buffers => 1 barrier/diag. 4-deep register
// prefetch of the per-thread cost row hides L2 latency.
// ---------------------------------------------------------------------------
__device__ __forceinline__ float ldc_clamped(const float* __restrict__ row, int i) {
    i = min(max(i, 0), T2 - 1);
    return __ldg(row + i);
}

__global__ __launch_bounds__(T1) void dtw_kernel(const int* __restrict__ len_a,
                                                 const int* __restrict__ len_b) {
    const int b = blockIdx.x;
    const int j = threadIdx.x;                 // 0..255

    __shared__ float sbuf[3 * (T1 + 1)];       // three diag buffers of 257

    const float* __restrict__ crow = g_cost + (size_t)(b * T1 + j) * T2;

    // Init: diag(-1) = pc0 (all BIG); diag(-2) = pcp0 (BIG except [0]=0)
    sbuf[2 * (T1 + 1) + j] = BIGF;
    sbuf[1 * (T1 + 1) + j] = (j == 0) ? 0.0f : BIGF;
    if (j == 0) {
        sbuf[2 * (T1 + 1) + T1] = BIGF;
        sbuf[1 * (T1 + 1) + T1] = BIGF;
    }

    const int la = len_a[b];
    const int lb = len_b[b];
    const int dtarget = la + lb - 2;
    const bool wr = (j == la - 1);

    int pwo = 2 * (T1 + 1);   // diag d-1 ("pc")
    int p1o = 1 * (T1 + 1);   // diag d-2 ("pcp")
    int p2o = 0;              // write target (diag d)
    int dcur = 0;

    __syncthreads();

    // softmin over exactly the reference's 3-value multiset:
    // {v0,v1,v2} == {max(v0,v1), min(min(v0,v1),v2), max(min(v0,v1),v2)}  (exact)
#define STEP(CD) do {                                                        \
        float v0 = sbuf[p1o + j];                                            \
        float v1 = sbuf[pwo + j + 1] + WPF;                                  \
        float v2 = sbuf[pwo + j] + WPF;                                      \
        float mn01 = fminf(v0, v1);                                          \
        float mx01 = fmaxf(v0, v1);                                          \
        float m    = fminf(mn01, v2);                                        \
        float oth  = fmaxf(mn01, v2);                                        \
        float s = 1.0f + __expf((m - mx01) * 100.0f)                         \
                       + __expf((m - oth)  * 100.0f);                        \
        float nv = (CD) + (m - 0.01f * __logf(s));                           \
        sbuf[p2o + j + 1] = nv;                                              \
        if (j == 0) sbuf[p2o] = BIGF;                                        \
        if (wr && dcur == dtarget) g_loss[b] = nv;                           \
        __syncthreads();                                                     \
        int _t = p2o; p2o = p1o; p1o = pwo; pwo = _t;                        \
        dcur++;                                                              \
    } while (0)

    // Prime the 4-deep cost pipeline (i = d - j, clamped exactly like reference)
    float c0 = ldc_clamped(crow, 0 - j);
    float c1 = ldc_clamped(crow, 1 - j);
    float c2 = ldc_clamped(crow, 2 - j);
    float c3 = ldc_clamped(crow, 3 - j);

    const int NGRP = NDIAG / 4;   // 319 full groups => d = 0..1275
    for (int g = 0; g < NGRP; g++) {
        int ip = dcur + 4 - j;
        float n0 = ldc_clamped(crow, ip);
        float n1 = ldc_clamped(crow, ip + 1);
        float n2 = ldc_clamped(crow, ip + 2);
        float n3 = ldc_clamped(crow, ip + 3);
        STEP(c0); STEP(c1); STEP(c2); STEP(c3);
        c0 = n0; c1 = n1; c2 = n2; c3 = n3;
    }
    // Remainder: d = 1276, 1277, 1278
    STEP(c0); STEP(c1); STEP(c2);
#undef STEP
}

// ---------------------------------------------------------------------------
// Phase 3: deterministic fixed-order reduction of the 8 per-batch losses.
// ---------------------------------------------------------------------------
__global__ void reduce_kernel(float* __restrict__ out) {
    float s = 0.0f;
#pragma unroll
    for (int i = 0; i < BB; i++) s += g_loss[i];
    out[0] = s;
}

// ---------------------------------------------------------------------------
extern "C" void kernel_launch(void* const* d_in, const int* in_sizes, int n_in,
                              void* d_out, int out_size) {
    (void)in_sizes; (void)n_in; (void)out_size;
    const float* fa = (const float*)d_in[0];   // fea_a  [8,256,128] f32
    const int*   la = (const int*)  d_in[1];   // len_a  [8] i32
    const float* fb = (const float*)d_in[2];   // fea_b  [8,1024,128] f32
    const int*   lb = (const int*)  d_in[3];   // len_b  [8] i32

    dim3 g1(T2 / TI, T1 / TJ, BB);             // (8,4,8) = 256 blocks
    cost_kernel<<<g1, 256>>>(fa, fb);
    dtw_kernel<<<BB, T1>>>(la, lb);
    reduce_kernel<<<1, 1>>>((float*)d_out);
}

// round 11
// speedup vs baseline: 1.0038x; 1.0009x over previous
#include <cuda_runtime.h>
#include <cuda_bf16.h>

// Problem constants (fixed by setup_inputs)
#define BB 8
#define T1 256
#define T2 1024
#define CC 128
#define NDIAG (T1 + T2 - 1)   // 1279

#define BIGF 10000000.0f
#define WPF  1.0f

// Phase-1 tiling
#define TJ 64
#define TI 128
#define KC 16

// Scratch (allocation-free rule: __device__ globals)
__device__ float g_cost[BB * T1 * T2];   // [b][j][i]  (T1-major => each DTW thread reads its own contiguous row)
__device__ float g_loss[BB];

// ---------------------------------------------------------------------------
// Phase 1: cost[b][j][i] = mean_c |A[b][j][c] - B[b][i][c]|
// GEMM-style smem tiling, 4x8 register blocking per thread, fp32 fma-pipe bound.
// ---------------------------------------------------------------------------
__global__ __launch_bounds__(256) void cost_kernel(const float* __restrict__ A,
                                                   const float* __restrict__ Bf) {
    __shared__ float As[KC][TJ + 4];   // [k][j], pad keeps 16B align, 2-way STS conflict max
    __shared__ float Bs[KC][TI + 4];   // [k][i]

    const int b  = blockIdx.z;
    const int jb = blockIdx.y * TJ;
    const int ib = blockIdx.x * TI;
    const int tid = threadIdx.x;

    const int kl = tid & 15;     // k lane for loads
    const int rl = tid >> 4;     // row lane for loads (0..15)

    const int tx = tid & 15;     // i-group
    const int ty = tid >> 4;     // j-group
    const int j0 = ty * 4;
    const int i0 = tx * 8;

    const float* Ag = A + (size_t)(b * T1 + jb) * CC;
    const float* Bg = Bf + (size_t)(b * T2 + ib) * CC;

    float acc[4][8];
#pragma unroll
    for (int u = 0; u < 4; u++)
#pragma unroll
        for (int v = 0; v < 8; v++) acc[u][v] = 0.0f;

    for (int c0 = 0; c0 < CC; c0 += KC) {
        // Load A tile: 64 rows x 16 k (4 elems/thread), coalesced 64B per row-chunk
#pragma unroll
        for (int p = 0; p < 4; p++) {
            int jj = rl + p * 16;
            As[kl][jj] = Ag[jj * CC + c0 + kl];
        }
        // Load B tile: 128 rows x 16 k (8 elems/thread)
#pragma unroll
        for (int p = 0; p < 8; p++) {
            int ii = rl + p * 16;
            Bs[kl][ii] = Bg[ii * CC + c0 + kl];
        }
        __syncthreads();

#pragma unroll
        for (int kk = 0; kk < KC; kk++) {
            float4 a4 = *(const float4*)&As[kk][j0];
            float4 b0 = *(const float4*)&Bs[kk][i0];
            float4 b1 = *(const float4*)&Bs[kk][i0 + 4];
            float av[4] = {a4.x, a4.y, a4.z, a4.w};
            float bv[8] = {b0.x, b0.y, b0.z, b0.w, b1.x, b1.y, b1.z, b1.w};
#pragma unroll
            for (int u = 0; u < 4; u++)
#pragma unroll
                for (int v = 0; v < 8; v++)
                    acc[u][v] += fabsf(av[u] - bv[v]);
        }
        __syncthreads();
    }

    const float sc = 1.0f / (float)CC;
#pragma unroll
    for (int u = 0; u < 4; u++) {
        float* dst = g_cost + (size_t)((b * T1 + jb + j0 + u) * T2) + ib + i0;
        float4 o0 = make_float4(acc[u][0] * sc, acc[u][1] * sc, acc[u][2] * sc, acc[u][3] * sc);
        float4 o1 = make_float4(acc[u][4] * sc, acc[u][5] * sc, acc[u][6] * sc, acc[u][7] * sc);
        *(float4*)dst = o0;
        *(float4*)(dst + 4) = o1;
    }
}

// ---------------------------------------------------------------------------
// Phase 2: anti-diagonal soft-DTW wavefront. One block per batch, one thread
// per j-column. 3 rotating smem diag buffers => 1 barrier/diag. 4-deep register
// prefetch of the per-thread cost row hides L2 latency.
// ---------------------------------------------------------------------------
__device__ __forceinline__ float ldc_clamped(const float* __restrict__ row, int i) {
    i = min(max(i, 0), T2 - 1);
    return __ldg(row + i);
}

__global__ __launch_bounds__(T1) void dtw_kernel(const int* __restrict__ len_a,
                                                 const int* __restrict__ len_b) {
    const int b = blockIdx.x;
    const int j = threadIdx.x;                 // 0..255

    __shared__ float sbuf[3 * (T1 + 1)];       // three diag buffers of 257

    const float* __restrict__ crow = g_cost + (size_t)(b * T1 + j) * T2;

    // Init: diag(-1) = pc0 (all BIG); diag(-2) = pcp0 (BIG except [0]=0)
    sbuf[2 * (T1 + 1) + j] = BIGF;
    sbuf[1 * (T1 + 1) + j] = (j == 0) ? 0.0f : BIGF;
    if (j == 0) {
        sbuf[2 * (T1 + 1) + T1] = BIGF;
        sbuf[1 * (T1 + 1) + T1] = BIGF;
    }

    const int la = len_a[b];
    const int lb = len_b[b];
    const int dtarget = la + lb - 2;
    const bool wr = (j == la - 1);

    int pwo = 2 * (T1 + 1);   // diag d-1 ("pc")
    int p1o = 1 * (T1 + 1);   // diag d-2 ("pcp")
    int p2o = 0;              // write target (diag d)
    int dcur = 0;

    __syncthreads();

    // softmin over exactly the reference's 3-value multiset:
    // {v0,v1,v2} == {max(v0,v1), min(min(v0,v1),v2), max(min(v0,v1),v2)}  (exact)
#define STEP(CD) do {                                                        \
        float v0 = sbuf[p1o + j];                                            \
        float v1 = sbuf[pwo + j + 1] + WPF;                                  \
        float v2 = sbuf[pwo + j] + WPF;                                      \
        float mn01 = fminf(v0, v1);                                          \
        float mx01 = fmaxf(v0, v1);                                          \
        float m    = fminf(mn01, v2);                                        \
        float oth  = fmaxf(mn01, v2);                                        \
        float s = 1.0f + __expf((m - mx01) * 100.0f)                         \
                       + __expf((m - oth)  * 100.0f);                        \
        float nv = (CD) + (m - 0.01f * __logf(s));                           \
        sbuf[p2o + j + 1] = nv;                                              \
        if (j == 0) sbuf[p2o] = BIGF;                                        \
        if (wr && dcur == dtarget) g_loss[b] = nv;                           \
        __syncthreads();                                                     \
        int _t = p2o; p2o = p1o; p1o = pwo; pwo = _t;                        \
        dcur++;                                                              \
    } while (0)

    // Prime the 4-deep cost pipeline (i = d - j, clamped exactly like reference)
    float c0 = ldc_clamped(crow, 0 - j);
    float c1 = ldc_clamped(crow, 1 - j);
    float c2 = ldc_clamped(crow, 2 - j);
    float c3 = ldc_clamped(crow, 3 - j);

    const int NGRP = NDIAG / 4;   // 319 full groups => d = 0..1275
    for (int g = 0; g < NGRP; g++) {
        int ip = dcur + 4 - j;
        float n0 = ldc_clamped(crow, ip);
        float n1 = ldc_clamped(crow, ip + 1);
        float n2 = ldc_clamped(crow, ip + 2);
        float n3 = ldc_clamped(crow, ip + 3);
        STEP(c0); STEP(c1); STEP(c2); STEP(c3);
        c0 = n0; c1 = n1; c2 = n2; c3 = n3;
    }
    // Remainder: d = 1276, 1277, 1278
    STEP(c0); STEP(c1); STEP(c2);
#undef STEP
}

// ---------------------------------------------------------------------------
// Phase 3: deterministic fixed-order reduction of the 8 per-batch losses.
// ---------------------------------------------------------------------------
__global__ void reduce_kernel(float* __restrict__ out) {
    float s = 0.0f;
#pragma unroll
    for (int i = 0; i < BB; i++) s += g_loss[i];
    out[0] = s;
}

// ---------------------------------------------------------------------------
extern "C" void kernel_launch(void* const* d_in, const int* in_sizes, int n_in,
                              void* d_out, int out_size) {
    (void)in_sizes; (void)n_in; (void)out_size;
    const float* fa = (const float*)d_in[0];   // fea_a  [8,256,128] f32
    const int*   la = (const int*)  d_in[1];   // len_a  [8] i32
    const float* fb = (const float*)d_in[2];   // fea_b  [8,1024,128] f32
    const int*   lb = (const int*)  d_in[3];   // len_b  [8] i32

    dim3 g1(T2 / TI, T1 / TJ, BB);             // (8,4,8) = 256 blocks
    cost_kernel<<<g1, 256>>>(fa, fb);
    dtw_kernel<<<BB, T1>>>(la, lb);
    reduce_kernel<<<1, 1>>>((float*)d_out);
}

// round 12
// speedup vs baseline: 1.4962x; 1.4906x over previous
#include <cuda_runtime.h>
#include <cuda_bf16.h>

// Problem constants (fixed by setup_inputs)
#define BB 8
#define T1 256
#define T2 1024
#define CC 128
#define NDIAG (T1 + T2 - 1)   // 1279

#define BIGF 10000000.0f
#define WPF  1.0f

// Phase-1 tiling
#define TJ 64
#define TI 128
#define KC 16

// Scratch (allocation-free rule: __device__ globals)
__device__ float g_cost[BB * T1 * T2];   // [b][j][i]  (each DTW thread reads its own contiguous row)
__device__ float g_loss[BB];

// ---------------------------------------------------------------------------
// Phase 1: cost[b][j][i] = mean_c |A[b][j][c] - B[b][i][c]|
// GEMM-style smem tiling, 4x8 register blocking. Thread's 8 i-columns are
// split as two float4s at tx*4 and 64+tx*4 so the warp's B-tile LDS.128
// addresses are CONSECUTIVE (conflict-free), instead of the 4-way-conflicting
// stride-8 pattern.
// ---------------------------------------------------------------------------
__global__ __launch_bounds__(256) void cost_kernel(const float* __restrict__ A,
                                                   const float* __restrict__ Bf) {
    __shared__ float As[KC][TJ + 4];   // [k][j]
    __shared__ float Bs[KC][TI + 4];   // [k][i]

    const int b  = blockIdx.z;
    const int jb = blockIdx.y * TJ;
    const int ib = blockIdx.x * TI;
    const int tid = threadIdx.x;

    const int kl = tid & 15;     // k lane for loads
    const int rl = tid >> 4;     // row lane for loads (0..15)

    const int tx = tid & 15;     // i-group
    const int ty = tid >> 4;     // j-group
    const int j0 = ty * 4;
    const int ia = tx * 4;       // first float4 of i-columns
    const int ib2 = 64 + tx * 4; // second float4 of i-columns

    const float* Ag = A + (size_t)(b * T1 + jb) * CC;
    const float* Bg = Bf + (size_t)(b * T2 + ib) * CC;

    float acc[4][8];
#pragma unroll
    for (int u = 0; u < 4; u++)
#pragma unroll
        for (int v = 0; v < 8; v++) acc[u][v] = 0.0f;

    for (int c0 = 0; c0 < CC; c0 += KC) {
        // Load A tile: 64 rows x 16 k (4 elems/thread)
#pragma unroll
        for (int p = 0; p < 4; p++) {
            int jj = rl + p * 16;
            As[kl][jj] = Ag[jj * CC + c0 + kl];
        }
        // Load B tile: 128 rows x 16 k (8 elems/thread)
#pragma unroll
        for (int p = 0; p < 8; p++) {
            int ii = rl + p * 16;
            Bs[kl][ii] = Bg[ii * CC + c0 + kl];
        }
        __syncthreads();

#pragma unroll
        for (int kk = 0; kk < KC; kk++) {
            float4 a4 = *(const float4*)&As[kk][j0];
            float4 b0 = *(const float4*)&Bs[kk][ia];    // consecutive across warp
            float4 b1 = *(const float4*)&Bs[kk][ib2];   // consecutive across warp
            float av[4] = {a4.x, a4.y, a4.z, a4.w};
            float bv[8] = {b0.x, b0.y, b0.z, b0.w, b1.x, b1.y, b1.z, b1.w};
#pragma unroll
            for (int u = 0; u < 4; u++)
#pragma unroll
                for (int v = 0; v < 8; v++)
                    acc[u][v] += fabsf(av[u] - bv[v]);
        }
        __syncthreads();
    }

    const float sc = 1.0f / (float)CC;
#pragma unroll
    for (int u = 0; u < 4; u++) {
        float* dst = g_cost + (size_t)((b * T1 + jb + j0 + u) * T2) + ib;
        float4 o0 = make_float4(acc[u][0] * sc, acc[u][1] * sc, acc[u][2] * sc, acc[u][3] * sc);
        float4 o1 = make_float4(acc[u][4] * sc, acc[u][5] * sc, acc[u][6] * sc, acc[u][7] * sc);
        *(float4*)(dst + ia)  = o0;
        *(float4*)(dst + ib2) = o1;
    }
}

// ---------------------------------------------------------------------------
// Phase 2: register-resident anti-diagonal wavefront.
// Thread j owns array position j+1. Per diagonal it needs:
//   v1 = pc[j+1]+wp  -> own register my_pc
//   v2 = pc[j]  +wp  -> left neighbor's my_pc, via shfl_up (lcur)
//   v0 = pcp[j]      -> SAME shfl result one diag earlier (lprev, retained)
// Smem is used only for the 8 warp-boundary values per diag, double-buffered
// by diag parity. Exactly 1 shfl + 1 barrier per diagonal; boundary lanes add
// 1 LDS / 1 STS. Each block stops at its own dtarget.
// ---------------------------------------------------------------------------
__device__ __forceinline__ float ldc_clamped(const float* __restrict__ row, int i) {
    i = min(max(i, 0), T2 - 1);
    return __ldg(row + i);
}

__global__ __launch_bounds__(T1) void dtw_kernel(const int* __restrict__ len_a,
                                                 const int* __restrict__ len_b) {
    const int b    = blockIdx.x;
    const int j    = threadIdx.x;            // 0..255
    const int warp = j >> 5;
    const int lane = j & 31;

    __shared__ float slots[2][8];            // [diag parity][warp] boundary pc values

    const float* __restrict__ crow = g_cost + (size_t)(b * T1 + j) * T2;

    const int la = len_a[b];
    const int lb = len_b[b];
    const int dtarget = la + lb - 2;         // <= 1278
    const bool wr = (j == la - 1);

    float my_pc = BIGF;                      // pc0[j+1] = BIG
    float lprev = (j == 0) ? 0.0f : BIGF;    // pcp0[j]: 0 at pos 0, else BIG
    float resv  = 0.0f;

    if (j < 8) { slots[0][j] = BIGF; slots[1][j] = BIGF; }
    __syncthreads();

    // Prime the 4-deep cost prefetch pipeline (i = d - j, clamped like reference)
    float c0 = ldc_clamped(crow, 0 - j);
    float c1 = ldc_clamped(crow, 1 - j);
    float c2 = ldc_clamped(crow, 2 - j);
    float c3 = ldc_clamped(crow, 3 - j);

    int d = 0;
    const int ngrp = (dtarget >> 2) + 1;     // groups of 4 diags, covers d=0..dtarget

    // softmin over exactly the reference's 3-value multiset:
    // {v0,v1,v2} == {max(v0,v1), min(min(v0,v1),v2), max(min(v0,v1),v2)} (exact)
#define STEP(CD) do {                                                        \
        float lcur = __shfl_up_sync(0xffffffffu, my_pc, 1);                  \
        if (lane == 0)                                                       \
            lcur = (warp == 0) ? BIGF : slots[d & 1][warp - 1];              \
        float v1 = my_pc + WPF;                                              \
        float v2 = lcur + WPF;                                               \
        float mn01 = fminf(lprev, v1);                                       \
        float mx01 = fmaxf(lprev, v1);                                       \
        float m    = fminf(mn01, v2);                                        \
        float oth  = fmaxf(mn01, v2);                                        \
        float s = 1.0f + __expf((m - mx01) * 100.0f)                         \
                       + __expf((m - oth)  * 100.0f);                        \
        float nv = (CD) + (m - 0.01f * __logf(s));                           \
        if (lane == 31) slots[(d + 1) & 1][warp] = nv;                       \
        if (wr && d == dtarget) resv = nv;                                   \
        lprev = lcur; my_pc = nv;                                            \
        d++;                                                                 \
        __syncthreads();                                                     \
    } while (0)

    for (int g = 0; g < ngrp; g++) {
        int ip = d + 4 - j;
        float n0 = ldc_clamped(crow, ip);
        float n1 = ldc_clamped(crow, ip + 1);
        float n2 = ldc_clamped(crow, ip + 2);
        float n3 = ldc_clamped(crow, ip + 3);
        STEP(c0); STEP(c1); STEP(c2); STEP(c3);
        c0 = n0; c1 = n1; c2 = n2; c3 = n3;
    }
#undef STEP

    if (wr) g_loss[b] = resv;
}

// ---------------------------------------------------------------------------
// Phase 3: deterministic fixed-order reduction of the 8 per-batch losses.
// ---------------------------------------------------------------------------
__global__ void reduce_kernel(float* __restrict__ out) {
    float s = 0.0f;
#pragma unroll
    for (int i = 0; i < BB; i++) s += g_loss[i];
    out[0] = s;
}

// ---------------------------------------------------------------------------
extern "C" void kernel_launch(void* const* d_in, const int* in_sizes, int n_in,
                              void* d_out, int out_size) {
    (void)in_sizes; (void)n_in; (void)out_size;
    const float* fa = (const float*)d_in[0];   // fea_a  [8,256,128] f32
    const int*   la = (const int*)  d_in[1];   // len_a  [8] i32
    const float* fb = (const float*)d_in[2];   // fea_b  [8,1024,128] f32
    const int*   lb = (const int*)  d_in[3];   // len_b  [8] i32

    dim3 g1(T2 / TI, T1 / TJ, BB);             // (8,4,8) = 256 blocks
    cost_kernel<<<g1, 256>>>(fa, fb);
    dtw_kernel<<<BB, T1>>>(la, lb);
    reduce_kernel<<<1, 1>>>((float*)d_out);
}